// round 15
// baseline (speedup 1.0000x reference)
#include <cuda_runtime.h>
#include <cuda_fp16.h>

typedef unsigned int u32;
typedef unsigned short u16;

// LocalDeepRFMFull via mma.sync m16n8k16 fp16 (plain sm_103 PTX).
// PERSISTENT version: 296 CTAs (2/SM, one wave), stage-outer / row-inner.
// B/Wo/bias staged into smem ONCE per CTA-stage (was: once per row-stage).
// Inter-stage z lives in a 16MB __device__ scratch (L2-resident).
// Per warp: m32 x n128 tile (4m x 2n warp grid), single-pass fp16 main GEMM
// (Ah*Bh), single-pass z-GEMM (h*Woh), bias-initialized accumulators,
// packed fp16x2 tanh. Compute body identical to R14.

#define TPB       256
#define NSTAGE    4
#define NROWS     4096
#define NCTA      296
#define A_STRIDE  176               // 80 fp16 cols + pad -> 11 x 16B (conflict-free ldmatrix)
#define A_BYTES   (128*A_STRIDE)    // 22528
#define B_STRIDE  176
#define B_BYTES   (256*B_STRIDE)    // 45056
#define WO_STRIDE 528               // 256 fp16 cols + pad -> 33 x 16B
#define WO_BYTES  (8*WO_STRIDE)     // 4224
#define SMEM_TOTAL (A_BYTES + B_BYTES + WO_BYTES + 2*1024*4 + 256*4)  // 81024

// Prebuilt fp16 Wi image (cols 0..79) and Wo-hi image, per stage.
__device__ __align__(16) unsigned char g_Bimg[NSTAGE][B_BYTES];
__device__ __align__(16) unsigned char g_Wimg[NSTAGE][WO_BYTES];
// Inter-stage z scratch (fp32), one row per batch row. 16MB -> L2-resident.
__device__ __align__(16) float g_z[NROWS * 1024];

__device__ __forceinline__ u32 smem_u32(const void* p) {
    u32 a;
    asm("{ .reg .u64 t; cvta.to.shared.u64 t, %1; cvt.u32.u64 %0, t; }" : "=r"(a) : "l"(p));
    return a;
}
// pack: low half = fp16(lo), high half = fp16(hi)
__device__ __forceinline__ u32 pack2(float lo, float hi) {
    __half2 h = __floats2half2_rn(lo, hi);
    return *(u32*)&h;
}

#define LDSM4(R0,R1,R2,R3,ADDR) \
    asm volatile("ldmatrix.sync.aligned.m8n8.x4.shared.b16 {%0,%1,%2,%3}, [%4];" \
        : "=r"(R0),"=r"(R1),"=r"(R2),"=r"(R3) : "r"(ADDR))
#define LDSM2(R0,R1,ADDR) \
    asm volatile("ldmatrix.sync.aligned.m8n8.x2.shared.b16 {%0,%1}, [%2];" \
        : "=r"(R0),"=r"(R1) : "r"(ADDR))
// non-volatile: pure register op, ptxas schedules freely
#define MMA(D,A0,A1,A2,A3,B0,B1) \
    asm("mma.sync.aligned.m16n8k16.row.col.f32.f16.f16.f32 " \
        "{%0,%1,%2,%3}, {%4,%5,%6,%7}, {%8,%9}, {%0,%1,%2,%3};" \
        : "+f"((D)[0]),"+f"((D)[1]),"+f"((D)[2]),"+f"((D)[3]) \
        : "r"(A0),"r"(A1),"r"(A2),"r"(A3),"r"(B0),"r"(B1))
#define TANH2(R) asm("tanh.approx.f16x2 %0, %0;" : "+r"(R))
#define CPA16(DST, SRC) \
    asm volatile("cp.async.cg.shared.global [%0], [%1], 16;" :: "r"(DST), "l"(SRC) : "memory")

// ---------------- precompute: Wi fp16 image + Wo-hi image ----------------
__global__ void build_imgs_kernel(const float* __restrict__ Wi,
                                  const float* __restrict__ Wo) {
    const int s = blockIdx.x, r = threadIdx.x;
    const float* w = Wi + (size_t)(s * 256 + r) * 80;
    unsigned char* img = g_Bimg[s] + r * B_STRIDE;
    for (int c = 0; c < 80; c += 2)
        *(u32*)(img + 2 * c) = pack2(w[c], w[c + 1]);
    unsigned char* wim = g_Wimg[s];
    for (int c = 0; c < 8; ++c) {
        __half hh = __float2half_rn(Wo[(size_t)s * 2048 + c * 256 + r]);
        *(u16*)(wim + c * WO_STRIDE + 2 * r) = *(u16*)&hh;
    }
}

// ---------------- main kernel (persistent) ----------------
__global__ void __launch_bounds__(TPB, 2)
rfm_mma_kernel(const float* __restrict__ x, const float* __restrict__ bi,
               float* __restrict__ out)
{
    extern __shared__ __align__(16) unsigned char smem[];
    unsigned char* A_sm  = smem;                       // 128 x 80 fp16: xh(40)|zh(40)
    unsigned char* B_sm  = smem + A_BYTES;             // 256 x 80 fp16: Wi hi
    unsigned char* WO_sm = smem + A_BYTES + B_BYTES;   // 8 x 256 fp16: Wo hi
    float* ZP = (float*)(WO_sm + WO_BYTES);            // [2][1024] z partials
    float* BI = ZP + 2 * 1024;                         // [256]

    const int t = threadIdx.x, w = t >> 5, lane = t & 31;
    const int wm = w & 3, wn = w >> 2;                 // 4 x 2 warp grid
    const int rr = lane & 7, q = lane >> 3;

    const u32 A32 = smem_u32(A_sm), B32 = smem_u32(B_sm), W32 = smem_u32(WO_sm);

    // m32 tile per warp: rows 32*wm .. 32*wm+31
    const u32 aT = A32 + (u32)((32 * wm + rr + 8 * (q & 1)) * A_STRIDE + (q >> 1) * 16);
    const u32 bT = B32 + (u32)((rr + 8 * (q >> 1)) * B_STRIDE + (q & 1) * 16);
    const u32 wT = W32 + (u32)(rr * WO_STRIDE + (q & 1) * 16);

    for (int s = 0; s < NSTAGE; ++s) {
        // ---- stage prologue (ONCE per CTA-stage): B + Wo + bias into smem ----
        {
            const char* bsrc = (const char*)&g_Bimg[s][0];
            for (int i = t; i < B_BYTES / 16; i += TPB)
                CPA16(B32 + 16 * i, bsrc + 16 * i);
            const char* wsrc = (const char*)&g_Wimg[s][0];
            for (int i = t; i < WO_BYTES / 16; i += TPB)
                CPA16(W32 + 16 * i, wsrc + 16 * i);
            asm volatile("cp.async.commit_group;" ::: "memory");
        }
        BI[t] = bi[s * 256 + t];
        asm volatile("cp.async.wait_group 0;" ::: "memory");
        __syncthreads();

        // ---- row loop: this CTA's rows, strided ----
        for (int r = blockIdx.x; r < NROWS; r += NCTA) {
            const float* xr = x + (size_t)r * 1024;
            const float* zr = g_z + (size_t)r * 1024;

            // ---- rebuild A: xh cols 0..39, zh cols 40..79 ----
            if (s == 0) {
                for (int idx = t; idx < 128 * 20; idx += TPB) {
                    int g = idx / 20, p = idx - g * 20;
                    int basei = (8 * g - 16 + 2 * p) & 1023;  // even -> pair never wraps
                    float2 v = *(const float2*)(xr + basei);
                    u32 hp = pack2(v.x, v.y);
                    unsigned char* arow = A_sm + g * A_STRIDE;
                    *(u32*)(arow + 4 * p)      = hp;   // x hi
                    *(u32*)(arow + 80 + 4 * p) = hp;   // z hi (z starts = x)
                }
            } else {
                for (int idx = t; idx < 128 * 20; idx += TPB) {
                    int g = idx / 20, p = idx - g * 20;
                    int basei = (8 * g - 16 + 2 * p) & 1023;
                    float2 xv = *(const float2*)(xr + basei);
                    float2 zv = *(const float2*)(zr + basei);
                    unsigned char* arow = A_sm + g * A_STRIDE;
                    *(u32*)(arow + 4 * p)      = pack2(xv.x, xv.y);
                    *(u32*)(arow + 80 + 4 * p) = pack2(zv.x, zv.y);
                }
            }
            __syncthreads();

            // ---- hoist A fragments: 2 m-tiles x 5 k16-chunks = 40 regs ----
            u32 A[2][5][4];
            #pragma unroll
            for (int mt = 0; mt < 2; ++mt)
                #pragma unroll
                for (int ch = 0; ch < 5; ++ch)
                    LDSM4(A[mt][ch][0], A[mt][ch][1], A[mt][ch][2], A[mt][ch][3],
                          aT + (u32)(mt * 16 * A_STRIDE + ch * 32));

            float zacc[2][4] = {{0,0,0,0},{0,0,0,0}};

            // ---- this warp's 4 n-chunks: nc = 4*wn + inc ----
            #pragma unroll
            for (int inc = 0; inc < 4; ++inc) {
                const int nc = 4 * wn + inc;
                const u32 bBase = bT + (u32)(nc * 32 * B_STRIDE);

                // n16-half 0: 5 LDSM4, then 20 MMAs
                u32 Bf[5][4];
                #pragma unroll
                for (int ch = 0; ch < 5; ++ch)
                    LDSM4(Bf[ch][0], Bf[ch][1], Bf[ch][2], Bf[ch][3], bBase + ch * 32);

                // d initialized with bias (fills the LDSM shadow)
                float d[2][4][4];
                #pragma unroll
                for (int j = 0; j < 4; ++j) {
                    const int lc = nc * 32 + j * 8 + 2 * (lane & 3);
                    float2 bp = *(const float2*)&BI[lc];
                    #pragma unroll
                    for (int mt = 0; mt < 2; ++mt) {
                        d[mt][j][0] = bp.x; d[mt][j][1] = bp.y;
                        d[mt][j][2] = bp.x; d[mt][j][3] = bp.y;
                    }
                }

                #pragma unroll
                for (int ch = 0; ch < 5; ++ch)
                    #pragma unroll
                    for (int mt = 0; mt < 2; ++mt) {
                        MMA(d[mt][0], A[mt][ch][0],A[mt][ch][1],A[mt][ch][2],A[mt][ch][3],
                            Bf[ch][0],Bf[ch][1]);
                        MMA(d[mt][1], A[mt][ch][0],A[mt][ch][1],A[mt][ch][2],A[mt][ch][3],
                            Bf[ch][2],Bf[ch][3]);
                    }

                // n16-half 1: 5 LDSM4, Wo frags in the shadow, 20 MMAs
                u32 Bg[5][4];
                #pragma unroll
                for (int ch = 0; ch < 5; ++ch)
                    LDSM4(Bg[ch][0], Bg[ch][1], Bg[ch][2], Bg[ch][3],
                          bBase + 16 * B_STRIDE + ch * 32);

                u32 bh0a,bh0b,bh1a,bh1b;
                LDSM2(bh0a,bh0b, wT + (u32)(nc * 64));
                LDSM2(bh1a,bh1b, wT + (u32)(nc * 64 + 32));

                #pragma unroll
                for (int ch = 0; ch < 5; ++ch)
                    #pragma unroll
                    for (int mt = 0; mt < 2; ++mt) {
                        MMA(d[mt][2], A[mt][ch][0],A[mt][ch][1],A[mt][ch][2],A[mt][ch][3],
                            Bg[ch][0],Bg[ch][1]);
                        MMA(d[mt][3], A[mt][ch][0],A[mt][ch][1],A[mt][ch][2],A[mt][ch][3],
                            Bg[ch][2],Bg[ch][3]);
                    }

                // ---- epilogue per m-tile: pack, fp16x2 tanh, z-MMA (Wo-hi only) ----
                #pragma unroll
                for (int mt = 0; mt < 2; ++mt) {
                    u32 h[8];
                    #pragma unroll
                    for (int j = 0; j < 4; ++j) {
                        u32 hp0 = pack2(d[mt][j][0], d[mt][j][1]);
                        u32 hp1 = pack2(d[mt][j][2], d[mt][j][3]);
                        TANH2(hp0); TANH2(hp1);
                        h[2*j] = hp0; h[2*j+1] = hp1;
                    }
                    MMA(zacc[mt], h[0],h[1],h[2],h[3], bh0a,bh0b);
                    MMA(zacc[mt], h[4],h[5],h[6],h[7], bh1a,bh1b);
                }
            }

            // ---- store z partials (flat idx = g*8+c) ----
            {
                float* zp = ZP + wn * 1024;
                const int c0 = 2 * (lane & 3);
                #pragma unroll
                for (int mt = 0; mt < 2; ++mt) {
                    const int g = 32 * wm + 16 * mt + (lane >> 2);
                    *(float2*)&zp[g * 8 + c0]       = make_float2(zacc[mt][0], zacc[mt][1]);
                    *(float2*)&zp[(g + 8) * 8 + c0] = make_float2(zacc[mt][2], zacc[mt][3]);
                }
            }
            __syncthreads();   // ZP ready (also: all A_sm reads done before next rebuild)

            // ---- reduce partials -> z scratch (or final out) ----
            float* dst = (s < NSTAGE - 1) ? (g_z + (size_t)r * 1024)
                                          : (out + (size_t)r * 1024);
            for (int i = t; i < 1024; i += TPB)
                dst[i] = ZP[i] + ZP[1024 + i];
            // next row's rebuild writes A_sm only after all warps pass the barrier
            // at its end of mainloop; ZP overwrite guarded by next row's post-store
            // barrier ordering (writes happen after this loop's reads complete via
            // the __syncthreads above on the following iteration's path).
            __syncthreads();
        }
    }
}

extern "C" void kernel_launch(void* const* d_in, const int* in_sizes, int n_in,
                              void* d_out, int out_size)
{
    const float* x  = (const float*)d_in[0];   // [4096, 1024]
    const float* Wi = (const float*)d_in[1];   // [4, 256, 80]
    const float* bi = (const float*)d_in[2];   // [4, 256]
    const float* Wo = (const float*)d_in[3];   // [4, 8, 256]
    float* out = (float*)d_out;                // [4096, 1024]

    cudaFuncSetAttribute(rfm_mma_kernel, cudaFuncAttributeMaxDynamicSharedMemorySize, SMEM_TOTAL);

    build_imgs_kernel<<<NSTAGE, 256>>>(Wi, Wo);
    rfm_mma_kernel<<<NCTA, TPB, SMEM_TOTAL>>>(x, bi, out);
}